// round 15
// baseline (speedup 1.0000x reference)
#include <cuda_runtime.h>
#include <cuda_fp16.h>
#include <cstdint>

// Problem constants
#define BATCH 256
#define HWDIM 128
#define PO    63
#define FTOT  63504
#define NHID  256
#define FANIN 512
#define NOUT  10

// s_img pitch in halfs: 130 = 65 words == 1 (mod 32) -> consecutive image
// rows rotate banks by 1 (R14 win: removed 4-8 way im2col LDS conflicts).
#define IPITCH 130

// Scratch (static device arrays per allocation rules)
__device__ float g_feats_T[(size_t)FTOT * BATCH];  // feats, [f][b] (written by conv)
__device__ float g_hidden[BATCH * NHID];           // hidden, [b][h]

__device__ __forceinline__ uint32_t pack2(__half lo, __half hi) {
    __half2 h = __halves2half2(lo, hi);
    return *(uint32_t*)&h;
}
__device__ __forceinline__ void mma16816(float d[4],
    uint32_t a0, uint32_t a1, uint32_t a2, uint32_t a3,
    uint32_t b0, uint32_t b1)
{
    asm volatile(
        "mma.sync.aligned.m16n8k16.row.col.f32.f16.f16.f32 "
        "{%0,%1,%2,%3}, {%4,%5,%6,%7}, {%8,%9}, {%0,%1,%2,%3};"
        : "+f"(d[0]), "+f"(d[1]), "+f"(d[2]), "+f"(d[3])
        : "r"(a0), "r"(a1), "r"(a2), "r"(a3), "r"(b0), "r"(b1));
}

// ============================================================
// Kernel A: conv3x3+bias+relu+maxpool via mma.sync (HMMA) im2col GEMM.
// R15 change: writes g_feats_T[f][b] DIRECTLY (same scatter-sector count as
// the old g_feats[b][f] writes — R13 proved scattered conv stores don't
// bind), eliminating the 11us transpose kernel entirely.
// ============================================================
__global__ __launch_bounds__(256) void conv_mma_kernel(
    const float* __restrict__ in,
    const float* __restrict__ cw,
    const float* __restrict__ cb)
{
    __shared__ __half s_img[3 * 18 * IPITCH];   // 13.7 KB staged band
    __shared__ __half s_w[16][32];              // zero-padded K
    __shared__ float  s_b[16];

    const int band = blockIdx.x;             // 0..7
    const int b    = blockIdx.y;
    const int qy0  = band * 8;
    const int P    = (band == 7) ? 7 : 8;    // pooled rows in band
    const int nq   = P * 63;
    const int ntile = (nq * 4 + 15) >> 4;    // 126 or 111
    const int nr   = 2 * P + 2;              // staged conv rows
    const int tid  = threadIdx.x;

    for (int i = tid; i < 512; i += 256) {
        int oc = i >> 5, k = i & 31;
        s_w[oc][k] = __float2half_rn(k < 27 ? cw[oc * 27 + k] : 0.0f);
    }
    if (tid < 16) s_b[tid] = cb[tid];

    // stage input band fp32 -> fp16: [3][nr][IPITCH]
    const float* gin = in + (size_t)b * 3 * HWDIM * HWDIM;
    for (int i = tid; i < 3 * nr * 64; i += 256) {
        int c   = i / (nr * 64);
        int rem = i - c * nr * 64;
        int rr  = rem >> 6, x2 = (rem & 63) * 2;
        float2 v = *(const float2*)&gin[((size_t)c * HWDIM + (2 * qy0 + rr)) * HWDIM + x2];
        *(__half2*)&s_img[(c * 18 + rr) * IPITCH + x2] = __floats2half2_rn(v.x, v.y);
    }
    __syncthreads();

    const int lane = tid & 31, wid = tid >> 5;
    const int r  = lane >> 2;            // A/D row group
    const int c0 = (lane & 3) * 2;       // A col base / D col base / B k base

    // per-lane fixed tap offsets (in halfs): j bit0=+1, bit1=+8, bit2=+16
    int offk[8];
    #pragma unroll
    for (int j = 0; j < 8; j++) {
        int k = c0 + (j & 1) + ((j >> 1) & 1) * 8 + (j >> 2) * 16;
        offk[j] = (k < 27) ? ((k / 9) * 18 + ((k % 9) / 3)) * IPITCH + (k % 3) : 0;
    }

    // B fragments [kstep][ochalf][reg]: b-rows k = c0+{0,1} (reg0), +8 (reg1)
    uint32_t Bf[2][2][2];
    #pragma unroll
    for (int ks = 0; ks < 2; ks++)
        #pragma unroll
        for (int oh = 0; oh < 2; oh++) {
            int oc = (lane >> 2) + 8 * oh;
            Bf[ks][oh][0] = *(const uint32_t*)&s_w[oc][c0 + 16 * ks];
            Bf[ks][oh][1] = *(const uint32_t*)&s_w[oc][c0 + 8 + 16 * ks];
        }

    // feats_T base for this (batch, band): f = oc*3969 + qy0*63 + q
    float* tbase = g_feats_T + ((size_t)qy0 * 63) * BATCH + b;

    for (int t = wid; t < ntile; t += 8) {
        // this lane's two pixel rows: pA = rows r, pB = r+8
        int pA = t * 16 + r, pB = pA + 8;
        int qA = pA >> 2; if (qA >= nq) qA = nq - 1;
        int qB = pB >> 2; if (qB >= nq) qB = nq - 1;
        int sA = pA & 3,  sB = pB & 3;
        int qyA = qA / 63, qxA = qA - qyA * 63;
        int qyB = qB / 63, qxB = qB - qyB * 63;
        int baseA = (2 * qyA + (sA >> 1)) * IPITCH + 2 * qxA + (sA & 1);
        int baseB = (2 * qyB + (sB >> 1)) * IPITCH + 2 * qxB + (sB & 1);

        float d[2][4] = {{0.f, 0.f, 0.f, 0.f}, {0.f, 0.f, 0.f, 0.f}};
        #pragma unroll
        for (int ks = 0; ks < 2; ks++) {
            uint32_t A0 = pack2(s_img[baseA + offk[4 * ks + 0]],
                                s_img[baseA + offk[4 * ks + 1]]);
            uint32_t A1 = pack2(s_img[baseB + offk[4 * ks + 0]],
                                s_img[baseB + offk[4 * ks + 1]]);
            uint32_t A2 = pack2(s_img[baseA + offk[4 * ks + 2]],
                                s_img[baseA + offk[4 * ks + 3]]);
            uint32_t A3 = pack2(s_img[baseB + offk[4 * ks + 2]],
                                s_img[baseB + offk[4 * ks + 3]]);
            mma16816(d[0], A0, A1, A2, A3, Bf[ks][0][0], Bf[ks][0][1]);
            mma16816(d[1], A0, A1, A2, A3, Bf[ks][1][0], Bf[ks][1][1]);
        }

        // maxpool over the 4 subpixels living in lane bits 2,3
        #pragma unroll
        for (int oh = 0; oh < 2; oh++)
            #pragma unroll
            for (int i = 0; i < 4; i++) {
                float v = d[oh][i];
                v = fmaxf(v, __shfl_xor_sync(0xffffffffu, v, 4));
                v = fmaxf(v, __shfl_xor_sync(0xffffffffu, v, 8));
                d[oh][i] = v;
            }

        // writers: lanes 0-3 -> q+0 (d0,d1) & q+2 (d2,d3); lanes 16-19 -> q+1 & q+3
        if ((lane & 15) < 4) {
            int q0 = t * 4 + (lane >> 4);
            int q2 = q0 + 2;
            #pragma unroll
            for (int oh = 0; oh < 2; oh++) {
                int oc = c0 + 8 * oh;
                if (q0 < nq) {
                    size_t fo = ((size_t)oc * 3969 + q0) * BATCH;
                    tbase[fo]          = fmaxf(d[oh][0] + s_b[oc], 0.f);
                    tbase[fo + 3969 * BATCH] = fmaxf(d[oh][1] + s_b[oc + 1], 0.f);
                }
                if (q2 < nq) {
                    size_t fo = ((size_t)oc * 3969 + q2) * BATCH;
                    tbase[fo]          = fmaxf(d[oh][2] + s_b[oc], 0.f);
                    tbase[fo + 3969 * BATCH] = fmaxf(d[oh][3] + s_b[oc + 1], 0.f);
                }
            }
        }
    }
}

// ============================================================
// Kernel B: hidden[b][h] = sigmoid(sum_k feats_T[idx[h,k]][b]*w[h,k]+hb[h])
// One CTA per h, 512 threads = (k-half, batch); coalesced 128B warp loads
// from L2-resident feats_T (measured ~13us).
// ============================================================
__global__ __launch_bounds__(512) void gather_hidden_kernel(
    const int*   __restrict__ hidx,
    const float* __restrict__ hw,
    const float* __restrict__ hb)
{
    __shared__ int   s_idx[FANIN];
    __shared__ float s_w[FANIN];
    __shared__ float s_part[BATCH];

    const int h = blockIdx.x, tid = threadIdx.x;
    s_idx[tid] = hidx[h * FANIN + tid];
    s_w[tid]   = hw[h * FANIN + tid];
    __syncthreads();

    const int b = tid & 255, half = tid >> 8, k0 = half * 256;
    float acc = 0.0f;
    #pragma unroll 8
    for (int k = 0; k < 256; k++)
        acc = fmaf(g_feats_T[(size_t)s_idx[k0 + k] * BATCH + b], s_w[k0 + k], acc);

    if (half) s_part[b] = acc;
    __syncthreads();
    if (!half)
        g_hidden[b * NHID + h] = 1.0f / (1.0f + expf(-(acc + s_part[b] + hb[h])));
}

// ============================================================
// Kernel C: out layer (measured 4.6-4.8us shape).
// ============================================================
__global__ __launch_bounds__(320) void out_kernel(
    const float* __restrict__ ow,
    const float* __restrict__ ob,
    float* __restrict__ out)
{
    const int b = blockIdx.x;
    const int warp = threadIdx.x >> 5, lane = threadIdx.x & 31;
    if (warp < NOUT) {
        float acc = 0.f;
        #pragma unroll
        for (int i = 0; i < NHID / 32; i++) {
            int j = i * 32 + lane;
            acc = fmaf(g_hidden[b * NHID + j], ow[warp * NHID + j], acc);
        }
        #pragma unroll
        for (int s = 16; s; s >>= 1) acc += __shfl_xor_sync(0xffffffffu, acc, s);
        if (lane == 0)
            out[b * NOUT + warp] = 1.f / (1.f + expf(-(acc + ob[warp])));
    }
}

// ============================================================
extern "C" void kernel_launch(void* const* d_in, const int* in_sizes, int n_in,
                              void* d_out, int out_size)
{
    const float* inputs = (const float*)d_in[0];
    const float* conv_w = (const float*)d_in[1];
    const float* conv_b = (const float*)d_in[2];
    const int*   hidx   = (const int*)d_in[3];
    const float* hw     = (const float*)d_in[4];
    const float* hb     = (const float*)d_in[5];
    const float* ow     = (const float*)d_in[6];
    const float* ob     = (const float*)d_in[7];

    conv_mma_kernel<<<dim3(8, BATCH), 256>>>(inputs, conv_w, conv_b);
    gather_hidden_kernel<<<NHID, 512>>>(hidx, hw, hb);
    out_kernel<<<BATCH, 320>>>(ow, ob, (float*)d_out);
}

// round 16
// speedup vs baseline: 1.4596x; 1.4596x over previous
#include <cuda_runtime.h>
#include <cuda_fp16.h>
#include <cstdint>

// Problem constants
#define BATCH 256
#define HWDIM 128
#define PO    63
#define FTOT  63504
#define NHID  256
#define FANIN 512
#define NOUT  10

// s_img pitch in halfs: 130 = 65 words == 1 (mod 32) -> consecutive image
// rows rotate banks by 1 (R14 win: removed 4-8 way im2col LDS conflicts).
#define IPITCH 130

// Scratch (static device arrays per allocation rules)
__device__ float g_feats[(size_t)BATCH * FTOT];    // pooled feats, [b][f]
__device__ float g_feats_T[(size_t)FTOT * BATCH];  // transposed,   [f][b]
__device__ float g_hidden[BATCH * NHID];           // hidden,       [b][h]

__device__ __forceinline__ uint32_t pack2(__half lo, __half hi) {
    __half2 h = __halves2half2(lo, hi);
    return *(uint32_t*)&h;
}
__device__ __forceinline__ void mma16816(float d[4],
    uint32_t a0, uint32_t a1, uint32_t a2, uint32_t a3,
    uint32_t b0, uint32_t b1)
{
    asm volatile(
        "mma.sync.aligned.m16n8k16.row.col.f32.f16.f16.f32 "
        "{%0,%1,%2,%3}, {%4,%5,%6,%7}, {%8,%9}, {%0,%1,%2,%3};"
        : "+f"(d[0]), "+f"(d[1]), "+f"(d[2]), "+f"(d[3])
        : "r"(a0), "r"(a1), "r"(a2), "r"(a3), "r"(b0), "r"(b1));
}

// ============================================================
// Kernel A: conv3x3+bias+relu+maxpool via mma.sync (HMMA) im2col GEMM.
// R16: M-row remap m = spart*4 + ql -> each lane's two D rows are the
// VERTICAL subpixel pair of one pooled point (in-register max), and the
// horizontal partner sits at lane^16 (ONE shfl). SHFL/tile 16 -> 4, one
// q/63 decode instead of two, baseB = baseA + IPITCH.
// Stores back to b-major g_feats (R15 showed T-direct stores cost +48us).
// ============================================================
__global__ __launch_bounds__(256) void conv_mma_kernel(
    const float* __restrict__ in,
    const float* __restrict__ cw,
    const float* __restrict__ cb)
{
    __shared__ __half s_img[3 * 18 * IPITCH];   // 13.7 KB staged band
    __shared__ __half s_w[16][32];              // zero-padded K
    __shared__ float  s_b[16];

    const int band = blockIdx.x;             // 0..7
    const int b    = blockIdx.y;
    const int qy0  = band * 8;
    const int P    = (band == 7) ? 7 : 8;    // pooled rows in band
    const int nq   = P * 63;
    const int ntile = (nq + 3) >> 2;         // 4 pooled points per tile
    const int nr   = 2 * P + 2;              // staged conv rows
    const int tid  = threadIdx.x;

    for (int i = tid; i < 512; i += 256) {
        int oc = i >> 5, k = i & 31;
        s_w[oc][k] = __float2half_rn(k < 27 ? cw[oc * 27 + k] : 0.0f);
    }
    if (tid < 16) s_b[tid] = cb[tid];

    // stage input band fp32 -> fp16: [3][nr][IPITCH]
    const float* gin = in + (size_t)b * 3 * HWDIM * HWDIM;
    for (int i = tid; i < 3 * nr * 64; i += 256) {
        int c   = i / (nr * 64);
        int rem = i - c * nr * 64;
        int rr  = rem >> 6, x2 = (rem & 63) * 2;
        float2 v = *(const float2*)&gin[((size_t)c * HWDIM + (2 * qy0 + rr)) * HWDIM + x2];
        *(__half2*)&s_img[(c * 18 + rr) * IPITCH + x2] = __floats2half2_rn(v.x, v.y);
    }
    __syncthreads();

    const int lane = tid & 31, wid = tid >> 5;
    const int r4 = lane >> 2;            // D row group 0..7
    const int c0 = (lane & 3) * 2;       // A col base / D col base / B k base
    const int ql = r4 & 3;               // pooled point within tile
    const int sx = r4 >> 2;              // horizontal subpixel 0/1

    // per-lane fixed tap offsets (in halfs): j bit0=+1, bit1=+8, bit2=+16
    int offk[8];
    #pragma unroll
    for (int j = 0; j < 8; j++) {
        int k = c0 + (j & 1) + ((j >> 1) & 1) * 8 + (j >> 2) * 16;
        offk[j] = (k < 27) ? ((k / 9) * 18 + ((k % 9) / 3)) * IPITCH + (k % 3) : 0;
    }

    // B fragments [kstep][ochalf][reg]: b-rows k = c0+{0,1} (reg0), +8 (reg1)
    uint32_t Bf[2][2][2];
    #pragma unroll
    for (int ks = 0; ks < 2; ks++)
        #pragma unroll
        for (int oh = 0; oh < 2; oh++) {
            int oc = (lane >> 2) + 8 * oh;
            Bf[ks][oh][0] = *(const uint32_t*)&s_w[oc][c0 + 16 * ks];
            Bf[ks][oh][1] = *(const uint32_t*)&s_w[oc][c0 + 8 + 16 * ks];
        }

    float* fbase = g_feats + (size_t)b * FTOT;

    for (int t = wid; t < ntile; t += 8) {
        // lane's pooled point; rows r4 (sy=0) and r4+8 (sy=1), col offset sx
        int q = t * 4 + ql;
        if (q >= nq) q = nq - 1;                 // partners share q -> safe
        int qy = q / 63, qx = q - qy * 63;
        int baseA = (2 * qy) * IPITCH + 2 * qx + sx;   // sy=0
        int baseB = baseA + IPITCH;                    // sy=1

        float d[2][4] = {{0.f, 0.f, 0.f, 0.f}, {0.f, 0.f, 0.f, 0.f}};
        #pragma unroll
        for (int ks = 0; ks < 2; ks++) {
            uint32_t A0 = pack2(s_img[baseA + offk[4 * ks + 0]],
                                s_img[baseA + offk[4 * ks + 1]]);
            uint32_t A1 = pack2(s_img[baseB + offk[4 * ks + 0]],
                                s_img[baseB + offk[4 * ks + 1]]);
            uint32_t A2 = pack2(s_img[baseA + offk[4 * ks + 2]],
                                s_img[baseA + offk[4 * ks + 3]]);
            uint32_t A3 = pack2(s_img[baseB + offk[4 * ks + 2]],
                                s_img[baseB + offk[4 * ks + 3]]);
            mma16816(d[0], A0, A1, A2, A3, Bf[ks][0][0], Bf[ks][0][1]);
            mma16816(d[1], A0, A1, A2, A3, Bf[ks][1][0], Bf[ks][1][1]);
        }

        // pool: vertical pair in-register (rows r4 / r4+8), horizontal via
        // ONE shfl to lane^16 (sx partner, same q)
        #pragma unroll
        for (int oh = 0; oh < 2; oh++) {
            float v0 = fmaxf(d[oh][0], d[oh][2]);
            float v1 = fmaxf(d[oh][1], d[oh][3]);
            v0 = fmaxf(v0, __shfl_xor_sync(0xffffffffu, v0, 16));
            v1 = fmaxf(v1, __shfl_xor_sync(0xffffffffu, v1, 16));
            d[oh][0] = v0; d[oh][1] = v1;
        }

        // writers: lanes 0..15 (sx=0 halves) hold pooled values for q
        if (lane < 16) {
            int qw = t * 4 + (lane >> 2);
            if (qw < nq) {
                int qg = qy0 * 63 + qw;
                #pragma unroll
                for (int oh = 0; oh < 2; oh++) {
                    int oc = c0 + 8 * oh;
                    fbase[(size_t)oc * 3969 + qg]       = fmaxf(d[oh][0] + s_b[oc], 0.f);
                    fbase[(size_t)(oc + 1) * 3969 + qg] = fmaxf(d[oh][1] + s_b[oc + 1], 0.f);
                }
            }
        }
    }
}

// ============================================================
// Kernel T: transpose g_feats[b][f] -> g_feats_T[f][b], fp32 (measured 11us).
// ============================================================
__global__ __launch_bounds__(256) void transpose_kernel()
{
    __shared__ float t[32][33];
    const int f0 = blockIdx.x * 32, b0 = blockIdx.y * 32;
    const int tx = threadIdx.x & 31, ty = threadIdx.x >> 5;

    #pragma unroll
    for (int j = 0; j < 4; j++) {
        int f = f0 + tx, b = b0 + ty + 8 * j;
        t[ty + 8 * j][tx] = (f < FTOT) ? g_feats[(size_t)b * FTOT + f] : 0.0f;
    }
    __syncthreads();
    #pragma unroll
    for (int j = 0; j < 4; j++) {
        int f = f0 + ty + 8 * j, b = b0 + tx;
        if (f < FTOT) g_feats_T[(size_t)f * BATCH + b] = t[tx][ty + 8 * j];
    }
}

// ============================================================
// Kernel B: gather-dot hidden (measured ~13us).
// ============================================================
__global__ __launch_bounds__(512) void gather_hidden_kernel(
    const int*   __restrict__ hidx,
    const float* __restrict__ hw,
    const float* __restrict__ hb)
{
    __shared__ int   s_idx[FANIN];
    __shared__ float s_w[FANIN];
    __shared__ float s_part[BATCH];

    const int h = blockIdx.x, tid = threadIdx.x;
    s_idx[tid] = hidx[h * FANIN + tid];
    s_w[tid]   = hw[h * FANIN + tid];
    __syncthreads();

    const int b = tid & 255, half = tid >> 8, k0 = half * 256;
    float acc = 0.0f;
    #pragma unroll 8
    for (int k = 0; k < 256; k++)
        acc = fmaf(g_feats_T[(size_t)s_idx[k0 + k] * BATCH + b], s_w[k0 + k], acc);

    if (half) s_part[b] = acc;
    __syncthreads();
    if (!half)
        g_hidden[b * NHID + h] = 1.0f / (1.0f + expf(-(acc + s_part[b] + hb[h])));
}

// ============================================================
// Kernel C: out layer (measured 4.6-4.8us shape).
// ============================================================
__global__ __launch_bounds__(320) void out_kernel(
    const float* __restrict__ ow,
    const float* __restrict__ ob,
    float* __restrict__ out)
{
    const int b = blockIdx.x;
    const int warp = threadIdx.x >> 5, lane = threadIdx.x & 31;
    if (warp < NOUT) {
        float acc = 0.f;
        #pragma unroll
        for (int i = 0; i < NHID / 32; i++) {
            int j = i * 32 + lane;
            acc = fmaf(g_hidden[b * NHID + j], ow[warp * NHID + j], acc);
        }
        #pragma unroll
        for (int s = 16; s; s >>= 1) acc += __shfl_xor_sync(0xffffffffu, acc, s);
        if (lane == 0)
            out[b * NOUT + warp] = 1.f / (1.f + expf(-(acc + ob[warp])));
    }
}

// ============================================================
extern "C" void kernel_launch(void* const* d_in, const int* in_sizes, int n_in,
                              void* d_out, int out_size)
{
    const float* inputs = (const float*)d_in[0];
    const float* conv_w = (const float*)d_in[1];
    const float* conv_b = (const float*)d_in[2];
    const int*   hidx   = (const int*)d_in[3];
    const float* hw     = (const float*)d_in[4];
    const float* hb     = (const float*)d_in[5];
    const float* ow     = (const float*)d_in[6];
    const float* ob     = (const float*)d_in[7];

    conv_mma_kernel<<<dim3(8, BATCH), 256>>>(inputs, conv_w, conv_b);
    transpose_kernel<<<dim3((FTOT + 31) / 32, BATCH / 32), 256>>>();
    gather_hidden_kernel<<<NHID, 512>>>(hidx, hw, hb);
    out_kernel<<<BATCH, 320>>>(ow, ob, (float*)d_out);
}